// round 5
// baseline (speedup 1.0000x reference)
#include <cuda_runtime.h>

// TFFastSpeechLengthRegulator: out[b,t,:] = hidden[b, idx(b,t), :] * (t < total[b]),
// mask[b,t] = (t < total[b]), where idx = searchsorted_right(cumsum(dur[b]), t).
//
// Shapes (fixed by dataset): B=32, L=1024, H=384, dur in [0,8).
// Output buffer = out (B*T*H f32) followed by mask (B*T f32); T recovered from out_size.

#define BB 32
#define LL 1024
#define HH 384
#define HV (HH / 4)      // 96 float4 per row
#define TMAX (7 * LL)    // durations < 8 -> total <= 7*1024

// Scratch (no cudaMalloc allowed): inverse index map + per-batch totals.
__device__ int g_idx[BB * TMAX];
__device__ int g_total[BB];

// Streaming 128-bit store (evict-first): out is write-once, never re-read,
// so keep it from displacing the reused hidden-state rows in L2.
__device__ __forceinline__ void stg_cs_v4(float4* p, float4 v) {
    asm volatile("st.global.cs.v4.f32 [%0], {%1,%2,%3,%4};"
                 :: "l"(p), "f"(v.x), "f"(v.y), "f"(v.z), "f"(v.w) : "memory");
}

// Phase 1: per-batch inclusive scan of durations (1024 threads, Hillis-Steele),
// then scatter the inverse map: idx[t] = l for t in [cum[l]-d, cum[l]).
// searchsorted(c, t, 'right') == number of c[j] <= t == exactly this map
// (zero-duration rows produce an empty range, matching 'right' semantics).
__global__ void lr_scan_kernel(const int* __restrict__ dur) {
    __shared__ int s[LL];
    const int b = blockIdx.x;
    const int l = threadIdx.x;
    const int d = dur[b * LL + l];
    s[l] = d;
    __syncthreads();
    #pragma unroll
    for (int off = 1; off < LL; off <<= 1) {
        int add = (l >= off) ? s[l - off] : 0;
        __syncthreads();
        s[l] += add;
        __syncthreads();
    }
    const int end   = s[l];
    const int start = end - d;
    if (l == LL - 1) g_total[b] = end;
    int* __restrict__ gi = g_idx + b * TMAX;
    for (int t = start; t < end; ++t) gi[t] = l;
}

// Phase 2: coalesced float4 gather. One 384-thread block handles 4 output rows
// of one batch (2D grid: x = row-quad, y = batch). Rows with t >= total get
// zeros (output buffer is poisoned pre-run, so every element must be written).
// All flat indices fit in int32 (max ~88M elements).
__global__ __launch_bounds__(384) void lr_gather_kernel(
    const float4* __restrict__ hid,   // [B, L, HV]
    float4* __restrict__ out,         // [B, T, HV]
    float*  __restrict__ mask,        // [B, T]
    int T)
{
    const int b   = blockIdx.y;
    const int sub = threadIdx.x / HV;          // 0..3
    const int col = threadIdx.x - sub * HV;    // 0..95
    const int t   = blockIdx.x * 4 + sub;
    if (t >= T) return;

    const int total = __ldg(&g_total[b]);
    const int bt    = b * T + t;               // row id, < 32*7168

    float4 v = make_float4(0.f, 0.f, 0.f, 0.f);
    if (t < total) {
        const int idx = __ldg(&g_idx[b * TMAX + t]);
        const float4* __restrict__ src = hid + (b * LL + idx) * HV;
        v = src[col];
    }
    stg_cs_v4(out + bt * HV + col, v);
    if (col == 0)
        mask[bt] = (t < total) ? 1.0f : 0.0f;
}

extern "C" void kernel_launch(void* const* d_in, const int* in_sizes, int n_in,
                              void* d_out, int out_size) {
    const float4* hid = (const float4*)d_in[0];   // encoder_hidden_states f32 [B,L,H]
    const int*    dur = (const int*)d_in[1];      // durations_gt i32 [B,L]

    // out_size = B*T*H + B*T = B*T*(H+1)
    const int T = out_size / (BB * (HH + 1));

    float4* out  = (float4*)d_out;
    float*  mask = (float*)d_out + (size_t)BB * T * HH;

    lr_scan_kernel<<<BB, LL>>>(dur);
    if (T > 0) {
        dim3 grid((T + 3) / 4, BB);
        lr_gather_kernel<<<grid, 384>>>(hid, out, mask, T);
    }
}

// round 10
// speedup vs baseline: 1.3861x; 1.3861x over previous
#include <cuda_runtime.h>

// TFFastSpeechLengthRegulator: out[b,t,:] = hidden[b, idx(b,t), :] * (t < total[b]),
// mask[b,t] = (t < total[b]), where idx = searchsorted_right(cumsum(dur[b]), t).
// B=32, L=1024, H=384, dur in [0,8). Output = out (B*T*H f32) ++ mask (B*T f32).

#define BB 32
#define LL 1024
#define HH 384
#define HV (HH / 4)      // 96 float4 per row
#define TMAX (7 * LL)    // durations < 8 -> total <= 7*1024
#define RPT 4            // output rows per thread (MLP)

// Scratch (no cudaMalloc allowed): inverse index map + per-batch totals.
__device__ int g_idx[BB * TMAX];
__device__ int g_total[BB];

// Streaming 128-bit store (evict-first): out is write-once, never re-read.
__device__ __forceinline__ void stg_cs_v4(float4* p, float4 v) {
    asm volatile("st.global.cs.v4.f32 [%0], {%1,%2,%3,%4};"
                 :: "l"(p), "f"(v.x), "f"(v.y), "f"(v.z), "f"(v.w) : "memory");
}

// Phase 1: per-batch inclusive scan (Hillis-Steele) + inverse-map scatter:
// idx[t] = l for t in [cum[l]-d, cum[l]) == searchsorted_right semantics.
__global__ void lr_scan_kernel(const int* __restrict__ dur) {
    __shared__ int s[LL];
    const int b = blockIdx.x;
    const int l = threadIdx.x;
    const int d = dur[b * LL + l];
    s[l] = d;
    __syncthreads();
    #pragma unroll
    for (int off = 1; off < LL; off <<= 1) {
        int add = (l >= off) ? s[l - off] : 0;
        __syncthreads();
        s[l] += add;
        __syncthreads();
    }
    const int end   = s[l];
    const int start = end - d;
    if (l == LL - 1) g_total[b] = end;
    int* __restrict__ gi = g_idx + b * TMAX;
    for (int t = start; t < end; ++t) gi[t] = l;
}

// Phase 2: coalesced float4 gather, RPT rows per thread for MLP.
// One 384-thread block covers 16 rows of one batch: thread handles
// col = tid%96 of rows t0+4u (u=0..3), t0 = blockIdx.x*16 + tid/96.
// All idx loads (warp-uniform) issue first, then RPT independent LDG.128,
// then RPT streaming stores. Rows t >= total get zeros (d_out is poisoned).
// Note: total <= T by construction (T = max_b total[b]), so t < total
// also implies t < T on the load path.
__global__ __launch_bounds__(384) void lr_gather_kernel(
    const float4* __restrict__ hid,   // [B, L, HV]
    float4* __restrict__ out,         // [B, T, HV]
    float*  __restrict__ mask,        // [B, T]
    int T)
{
    const int b   = blockIdx.y;
    const int sub = threadIdx.x / HV;          // 0..3
    const int col = threadIdx.x - sub * HV;    // 0..95
    const int t0  = blockIdx.x * (4 * RPT) + sub;

    const int total = __ldg(&g_total[b]);
    const float4* __restrict__ hb = hid + b * LL * HV;
    const int* __restrict__ gi = g_idx + b * TMAX;

    int idx[RPT];
    #pragma unroll
    for (int u = 0; u < RPT; ++u) {
        const int t = t0 + 4 * u;
        idx[u] = (t < total) ? __ldg(&gi[t]) : -1;
    }

    float4 v[RPT];
    #pragma unroll
    for (int u = 0; u < RPT; ++u) {
        v[u] = make_float4(0.f, 0.f, 0.f, 0.f);
        if (idx[u] >= 0) v[u] = hb[idx[u] * HV + col];
    }

    #pragma unroll
    for (int u = 0; u < RPT; ++u) {
        const int t = t0 + 4 * u;
        if (t < T) {
            const int bt = b * T + t;
            stg_cs_v4(out + bt * HV + col, v[u]);
            if (col == 0) mask[bt] = (t < total) ? 1.0f : 0.0f;
        }
    }
}

extern "C" void kernel_launch(void* const* d_in, const int* in_sizes, int n_in,
                              void* d_out, int out_size) {
    const float4* hid = (const float4*)d_in[0];   // encoder_hidden_states f32 [B,L,H]
    const int*    dur = (const int*)d_in[1];      // durations_gt i32 [B,L]

    // out_size = B*T*H + B*T = B*T*(H+1)
    const int T = out_size / (BB * (HH + 1));

    float4* out  = (float4*)d_out;
    float*  mask = (float*)d_out + (size_t)BB * T * HH;

    lr_scan_kernel<<<BB, LL>>>(dur);
    if (T > 0) {
        dim3 grid((T + 4 * RPT - 1) / (4 * RPT), BB);
        lr_gather_kernel<<<grid, 384>>>(hid, out, mask, T);
    }
}